// round 13
// baseline (speedup 1.0000x reference)
#include <cuda_runtime.h>
#include <cuda_bf16.h>
#include <cstdint>

#define ALPHA 0.2f
#define KDIM 4096
#define NDIM 1024
#define CH 16
#define NCHUNK (KDIM / CH)   // 256

// ---------------- scratch (__device__ globals; no allocs allowed) ----------
__device__ float g_s1[KDIM], g_s2[KDIM];
__device__ float g_ea[KDIM], g_ec[KDIM];        // exp(s1), exp(0.2 s1)
__device__ float g_eb[KDIM], g_ed[KDIM];        // exp(s2), exp(0.2 s2)
__device__ float g_sorted[KDIM];                // s2 ascending
__device__ int   g_sigma[KDIM];                 // sorted rank -> original index
__device__ float g_ebS[KDIM], g_edS[KDIM];      // eb/ed in sorted order
__device__ float g_sb[KDIM + 1], g_sd[KDIM + 1];// scalar global suffix sums
__device__ float g_sufB[(size_t)KDIM * NDIM];   // chunk-local vector suffix sums
__device__ float g_sufD[(size_t)KDIM * NDIM];
__device__ float g_carB[NCHUNK * NDIM];         // exclusive chunk-suffix carries
__device__ float g_carD[NCHUNK * NDIM];

__device__ __forceinline__ float4 suffix_shfl(float4 v, int lane) {
    #pragma unroll
    for (int o = 1; o < 32; o <<= 1) {
        float ux = __shfl_down_sync(0xffffffffu, v.x, o);
        float uy = __shfl_down_sync(0xffffffffu, v.y, o);
        float uz = __shfl_down_sync(0xffffffffu, v.z, o);
        float uw = __shfl_down_sync(0xffffffffu, v.w, o);
        if (lane + o < 32) { v.x += ux; v.y += uy; v.z += uz; v.w += uw; }
    }
    return v;
}

// ---------------------------------------------------------------------------
// K1: s1/s2 GEMV + exp factors. 1024 blocks x 4 rows, loads batched for MLP.
// ---------------------------------------------------------------------------
__global__ __launch_bounds__(256) void k_scores(const float* __restrict__ x,
                                                const float* __restrict__ w) {
    int b = blockIdx.x;           // 1024
    int t = threadIdx.x;          // 256 threads * float4 = 1024 cols
    int i0 = b * 4;
    const float4* w1 = reinterpret_cast<const float4*>(w);
    const float4* w2 = reinterpret_cast<const float4*>(w + NDIM);
    float4 a = __ldg(w1 + t);
    float4 bb = __ldg(w2 + t);
    float4 xv[4];
    #pragma unroll
    for (int r = 0; r < 4; r++)
        xv[r] = __ldg(reinterpret_cast<const float4*>(x + (size_t)(i0 + r) * NDIM) + t);

    __shared__ float sm1[4][8], sm2[4][8];
    #pragma unroll
    for (int r = 0; r < 4; r++) {
        float d1 = xv[r].x * a.x + xv[r].y * a.y + xv[r].z * a.z + xv[r].w * a.w;
        float d2 = xv[r].x * bb.x + xv[r].y * bb.y + xv[r].z * bb.z + xv[r].w * bb.w;
        #pragma unroll
        for (int o = 16; o > 0; o >>= 1) {
            d1 += __shfl_down_sync(0xffffffffu, d1, o);
            d2 += __shfl_down_sync(0xffffffffu, d2, o);
        }
        if ((t & 31) == 0) { sm1[r][t >> 5] = d1; sm2[r][t >> 5] = d2; }
    }
    __syncthreads();
    if (t < 4) {
        float s1 = 0.f, s2 = 0.f;
        #pragma unroll
        for (int q = 0; q < 8; q++) { s1 += sm1[t][q]; s2 += sm2[t][q]; }
        int i = i0 + t;
        g_s1[i] = s1;
        g_s2[i] = s2;
        g_ea[i] = __expf(s1);
        g_ec[i] = __expf(ALPHA * s1);
        g_eb[i] = __expf(s2);
        g_ed[i] = __expf(ALPHA * s2);
    }
}

// ---------------------------------------------------------------------------
// K2: ranks, 16 rows per block (256 blocks, ~4MB L2 traffic)
// ---------------------------------------------------------------------------
__global__ __launch_bounds__(256) void k_rank16() {
    int b = blockIdx.x;         // 256 blocks
    int tid = threadIdx.x;
    int i0 = b * 16;
    __shared__ float sv[16];
    __shared__ int scnt[16];
    if (tid < 16) { sv[tid] = g_s2[i0 + tid]; scnt[tid] = 0; }
    __syncthreads();
    int cnt[16];
    #pragma unroll
    for (int q = 0; q < 16; q++) cnt[q] = 0;
    for (int j = tid; j < KDIM; j += 256) {
        float u = g_s2[j];
        #pragma unroll
        for (int q = 0; q < 16; q++) {
            float v = sv[q];
            cnt[q] += (u < v) || (u == v && j < i0 + q);
        }
    }
    #pragma unroll
    for (int q = 0; q < 16; q++) {
        int r = cnt[q];
        #pragma unroll
        for (int o = 16; o > 0; o >>= 1) r += __shfl_down_sync(0xffffffffu, r, o);
        if ((tid & 31) == 0) atomicAdd(&scnt[q], r);
    }
    __syncthreads();
    if (tid < 16) {
        int r = scnt[tid];
        int i = i0 + tid;
        g_sorted[r] = sv[tid];
        g_sigma[r] = i;
        g_ebS[r] = g_eb[i];
        g_edS[r] = g_ed[i];
    }
}

// ---------------------------------------------------------------------------
// K3 (merged): blocks 0-255 = chunk-local vector suffix sums (scan);
// blocks 256-511 = carries computed independently from x (same accumulation
// order as the scan -> bitwise-identical totals); block 512 = scalar sscan.
// ---------------------------------------------------------------------------
__global__ __launch_bounds__(256, 2) void k_scancarry(const float* __restrict__ x) {
    int b = blockIdx.x;
    int tid = threadIdx.x;
    int lane = tid & 31, wq = tid >> 5;

    if (b < 256) {
        // ---- scan: block = chunk b ----
        int c = b;
        int col = tid * 4;
        __shared__ int ssig[CH];
        __shared__ float scb[CH], scd[CH];
        if (tid < CH) {
            int k = c * CH + tid;
            ssig[tid] = g_sigma[k];
            scb[tid] = g_ebS[k];
            scd[tid] = g_edS[k];
        }
        __syncthreads();
        float4 y[CH];
        #pragma unroll
        for (int r = 0; r < CH; r++)
            y[r] = __ldg(reinterpret_cast<const float4*>(x + (size_t)ssig[r] * NDIM + col));
        float4 aB = make_float4(0.f, 0.f, 0.f, 0.f);
        float4 aD = make_float4(0.f, 0.f, 0.f, 0.f);
        #pragma unroll
        for (int r = CH - 1; r >= 0; r--) {
            float cb = scb[r], cd = scd[r];
            aB.x = fmaf(cb, y[r].x, aB.x); aB.y = fmaf(cb, y[r].y, aB.y);
            aB.z = fmaf(cb, y[r].z, aB.z); aB.w = fmaf(cb, y[r].w, aB.w);
            aD.x = fmaf(cd, y[r].x, aD.x); aD.y = fmaf(cd, y[r].y, aD.y);
            aD.z = fmaf(cd, y[r].z, aD.z); aD.w = fmaf(cd, y[r].w, aD.w);
            size_t ro = (size_t)(c * CH + r) * NDIM + col;
            *reinterpret_cast<float4*>(g_sufB + ro) = aB;
            *reinterpret_cast<float4*>(g_sufD + ro) = aD;
        }
    } else if (b < 512) {
        // ---- carry: block = column quad; thread = chunk; totals from x ----
        int col = (b - 256) * 4;
        int c = tid;  // chunk
        __shared__ float4 wtB[8], wtD[8];

        // weights for chunk c (contiguous in sorted order)
        float4 cb4[4], cd4[4];
        int4 sg4[4];
        #pragma unroll
        for (int q = 0; q < 4; q++) {
            cb4[q] = *reinterpret_cast<const float4*>(g_ebS + c * CH + q * 4);
            cd4[q] = *reinterpret_cast<const float4*>(g_edS + c * CH + q * 4);
            sg4[q] = *reinterpret_cast<const int4*>(g_sigma + c * CH + q * 4);
        }
        int sg[16] = { sg4[0].x, sg4[0].y, sg4[0].z, sg4[0].w,
                       sg4[1].x, sg4[1].y, sg4[1].z, sg4[1].w,
                       sg4[2].x, sg4[2].y, sg4[2].z, sg4[2].w,
                       sg4[3].x, sg4[3].y, sg4[3].z, sg4[3].w };
        float cb[16] = { cb4[0].x, cb4[0].y, cb4[0].z, cb4[0].w,
                         cb4[1].x, cb4[1].y, cb4[1].z, cb4[1].w,
                         cb4[2].x, cb4[2].y, cb4[2].z, cb4[2].w,
                         cb4[3].x, cb4[3].y, cb4[3].z, cb4[3].w };
        float cd[16] = { cd4[0].x, cd4[0].y, cd4[0].z, cd4[0].w,
                         cd4[1].x, cd4[1].y, cd4[1].z, cd4[1].w,
                         cd4[2].x, cd4[2].y, cd4[2].z, cd4[2].w,
                         cd4[3].x, cd4[3].y, cd4[3].z, cd4[3].w };

        float4 y[CH];
        #pragma unroll
        for (int r = 0; r < CH; r++)
            y[r] = __ldg(reinterpret_cast<const float4*>(x + (size_t)sg[r] * NDIM + col));

        // chunk totals, SAME order as scan (r = 15 -> 0) => bitwise identical
        float4 tB = make_float4(0.f, 0.f, 0.f, 0.f);
        float4 tD = make_float4(0.f, 0.f, 0.f, 0.f);
        #pragma unroll
        for (int r = CH - 1; r >= 0; r--) {
            tB.x = fmaf(cb[r], y[r].x, tB.x); tB.y = fmaf(cb[r], y[r].y, tB.y);
            tB.z = fmaf(cb[r], y[r].z, tB.z); tB.w = fmaf(cb[r], y[r].w, tB.w);
            tD.x = fmaf(cd[r], y[r].x, tD.x); tD.y = fmaf(cd[r], y[r].y, tD.y);
            tD.z = fmaf(cd[r], y[r].z, tD.z); tD.w = fmaf(cd[r], y[r].w, tD.w);
        }

        float4 iB = suffix_shfl(tB, lane);  // inclusive suffix within warp
        float4 iD = suffix_shfl(tD, lane);
        if (lane == 0) { wtB[wq] = iB; wtD[wq] = iD; }
        __syncthreads();
        float4 gB = make_float4(0.f, 0.f, 0.f, 0.f);
        float4 gD = make_float4(0.f, 0.f, 0.f, 0.f);
        #pragma unroll
        for (int g = 0; g < 8; g++) {
            if (g > wq) {
                float4 vB = wtB[g], vD = wtD[g];
                gB.x += vB.x; gB.y += vB.y; gB.z += vB.z; gB.w += vB.w;
                gD.x += vD.x; gD.y += vD.y; gD.z += vD.z; gD.w += vD.w;
            }
        }
        float4 eB = make_float4(iB.x - tB.x + gB.x, iB.y - tB.y + gB.y,
                                iB.z - tB.z + gB.z, iB.w - tB.w + gB.w);
        float4 eD = make_float4(iD.x - tD.x + gD.x, iD.y - tD.y + gD.y,
                                iD.z - tD.z + gD.z, iD.w - tD.w + gD.w);
        *reinterpret_cast<float4*>(g_carB + (size_t)c * NDIM + col) = eB;
        *reinterpret_cast<float4*>(g_carD + (size_t)c * NDIM + col) = eD;
    } else {
        // ---- scalar suffix scans: thread t owns elems [16t, 16t+16) ----
        __shared__ float wtot[8], wsuf[8];
        #pragma unroll
        for (int pass = 0; pass < 2; pass++) {
            const float* src = pass ? g_edS : g_ebS;
            float* dst = pass ? g_sd : g_sb;
            float e[16];
            float tot = 0.f;
            #pragma unroll
            for (int q = 0; q < 16; q++) { e[q] = src[16 * tid + q]; tot += e[q]; }
            float v = tot;
            #pragma unroll
            for (int o = 1; o < 32; o <<= 1) {
                float u = __shfl_down_sync(0xffffffffu, v, o);
                if (lane + o < 32) v += u;
            }
            if (lane == 0) wtot[wq] = v;
            __syncthreads();
            if (wq == 0 && lane < 8) {
                float s = 0.f;
                #pragma unroll
                for (int q = 0; q < 8; q++) s += (q > lane) ? wtot[q] : 0.f;
                wsuf[lane] = s;
            }
            __syncthreads();
            float s = (v - tot) + wsuf[wq];
            #pragma unroll
            for (int q = 15; q >= 0; q--) {
                s += e[q];
                dst[16 * tid + q] = s;
            }
            if (tid == 0) dst[KDIM] = 0.f;
            __syncthreads();
        }
    }
}

// ---------------------------------------------------------------------------
// K4: outputs, 16 rows per block (256 blocks). TotD loaded once per block;
// suffix-table loads batched 4 rows deep.
// ---------------------------------------------------------------------------
__global__ __launch_bounds__(256) void k_out(float* __restrict__ out) {
    int b = blockIdx.x;
    int tid = threadIdx.x;
    int col = tid * 4;
    __shared__ int sT[16];
    __shared__ float sAZ[16], sCZ[16];

    float4 sD0 = *reinterpret_cast<const float4*>(g_sufD + col);
    float4 cD0 = *reinterpret_cast<const float4*>(g_carD + col);
    float4 tD = make_float4(sD0.x + cD0.x, sD0.y + cD0.y,
                            sD0.z + cD0.z, sD0.w + cD0.w);
    if (tid < 16) {
        int i = b * 16 + tid;
        float key = -g_s1[i];
        int lo = 0, hi = KDIM;
        while (lo < hi) {
            int mid = (lo + hi) >> 1;
            if (g_sorted[mid] <= key) lo = mid + 1;
            else hi = mid;
        }
        int t = lo;
        float a = g_ea[i], c = g_ec[i];
        float Z = a * g_sb[t] + c * (g_sd[0] - g_sd[t]);
        float rZ = 1.f / Z;
        sT[tid] = t;
        sAZ[tid] = a * rZ;
        sCZ[tid] = c * rZ;
    }
    __syncthreads();
    #pragma unroll
    for (int g = 0; g < 16; g += 4) {
        float4 sB[4], cB[4], sD[4], cD[4];
        #pragma unroll
        for (int q = 0; q < 4; q++) {
            int t = sT[g + q];
            int tt = (t < KDIM) ? t : 0;
            int ch = tt / CH;
            size_t ro = (size_t)tt * NDIM + col;
            size_t co = (size_t)ch * NDIM + col;
            sB[q] = *reinterpret_cast<const float4*>(g_sufB + ro);
            cB[q] = *reinterpret_cast<const float4*>(g_carB + co);
            sD[q] = *reinterpret_cast<const float4*>(g_sufD + ro);
            cD[q] = *reinterpret_cast<const float4*>(g_carD + co);
        }
        #pragma unroll
        for (int q = 0; q < 4; q++) {
            int r = g + q;
            float aZ = sAZ[r], cZ = sCZ[r];
            float m = (sT[r] < KDIM) ? 1.f : 0.f;
            float4 h;
            h.x = aZ * m * (sB[q].x + cB[q].x) + cZ * (tD.x - m * (sD[q].x + cD[q].x));
            h.y = aZ * m * (sB[q].y + cB[q].y) + cZ * (tD.y - m * (sD[q].y + cD[q].y));
            h.z = aZ * m * (sB[q].z + cB[q].z) + cZ * (tD.z - m * (sD[q].z + cD[q].z));
            h.w = aZ * m * (sB[q].w + cB[q].w) + cZ * (tD.w - m * (sD[q].w + cD[q].w));
            *reinterpret_cast<float4*>(out + (size_t)(b * 16 + r) * NDIM + col) = h;
        }
    }
}

// ---------------------------------------------------------------------------
extern "C" void kernel_launch(void* const* d_in, const int* in_sizes, int n_in,
                              void* d_out, int out_size) {
    const float* x = (const float*)d_in[0];   // (4096, 1024) fp32
    const float* w = (const float*)d_in[1];   // (2048, 1) fp32
    float* out = (float*)d_out;               // (4096, 1024) fp32

    k_scores<<<KDIM / 4, 256>>>(x, w);
    k_rank16<<<NCHUNK, 256>>>();
    k_scancarry<<<513, 256>>>(x);
    k_out<<<NCHUNK, 256>>>(out);
}

// round 14
// speedup vs baseline: 1.0324x; 1.0324x over previous
#include <cuda_runtime.h>
#include <cuda_bf16.h>
#include <cstdint>

#define ALPHA 0.2f
#define KDIM 4096
#define NDIM 1024
#define CH 16
#define NCHUNK (KDIM / CH)   // 256

// ---------------- scratch (__device__ globals; no allocs allowed) ----------
__device__ float g_s1[KDIM], g_s2[KDIM];
__device__ float g_ea[KDIM], g_ec[KDIM];        // exp(s1), exp(0.2 s1)
__device__ float g_eb[KDIM], g_ed[KDIM];        // exp(s2), exp(0.2 s2)
__device__ float g_sorted[KDIM];                // s2 ascending
__device__ int   g_sigma[KDIM];                 // sorted rank -> original index
__device__ float g_ebS[KDIM], g_edS[KDIM];      // eb/ed in sorted order
__device__ float g_sb[KDIM + 1], g_sd[KDIM + 1];// scalar global suffix sums
__device__ float g_sufB[(size_t)KDIM * NDIM];   // chunk-local vector suffix sums
__device__ float g_sufD[(size_t)KDIM * NDIM];
__device__ float g_carB[NCHUNK * NDIM];         // exclusive chunk-suffix carries
__device__ float g_carD[NCHUNK * NDIM];

__device__ __forceinline__ float4 suffix_shfl(float4 v, int lane) {
    #pragma unroll
    for (int o = 1; o < 32; o <<= 1) {
        float ux = __shfl_down_sync(0xffffffffu, v.x, o);
        float uy = __shfl_down_sync(0xffffffffu, v.y, o);
        float uz = __shfl_down_sync(0xffffffffu, v.z, o);
        float uw = __shfl_down_sync(0xffffffffu, v.w, o);
        if (lane + o < 32) { v.x += ux; v.y += uy; v.z += uz; v.w += uw; }
    }
    return v;
}

// ---------------------------------------------------------------------------
// K1: s1/s2 GEMV + exp factors. 1024 blocks x 4 rows, loads batched for MLP.
// ---------------------------------------------------------------------------
__global__ __launch_bounds__(256) void k_scores(const float* __restrict__ x,
                                                const float* __restrict__ w) {
    int b = blockIdx.x;           // 1024
    int t = threadIdx.x;          // 256 threads * float4 = 1024 cols
    int i0 = b * 4;
    const float4* w1 = reinterpret_cast<const float4*>(w);
    const float4* w2 = reinterpret_cast<const float4*>(w + NDIM);
    float4 a = __ldg(w1 + t);
    float4 bb = __ldg(w2 + t);
    float4 xv[4];
    #pragma unroll
    for (int r = 0; r < 4; r++)
        xv[r] = __ldg(reinterpret_cast<const float4*>(x + (size_t)(i0 + r) * NDIM) + t);

    __shared__ float sm1[4][8], sm2[4][8];
    #pragma unroll
    for (int r = 0; r < 4; r++) {
        float d1 = xv[r].x * a.x + xv[r].y * a.y + xv[r].z * a.z + xv[r].w * a.w;
        float d2 = xv[r].x * bb.x + xv[r].y * bb.y + xv[r].z * bb.z + xv[r].w * bb.w;
        #pragma unroll
        for (int o = 16; o > 0; o >>= 1) {
            d1 += __shfl_down_sync(0xffffffffu, d1, o);
            d2 += __shfl_down_sync(0xffffffffu, d2, o);
        }
        if ((t & 31) == 0) { sm1[r][t >> 5] = d1; sm2[r][t >> 5] = d2; }
    }
    __syncthreads();
    if (t < 4) {
        float s1 = 0.f, s2 = 0.f;
        #pragma unroll
        for (int q = 0; q < 8; q++) { s1 += sm1[t][q]; s2 += sm2[t][q]; }
        int i = i0 + t;
        g_s1[i] = s1;
        g_s2[i] = s2;
        g_ea[i] = __expf(s1);
        g_ec[i] = __expf(ALPHA * s1);
        g_eb[i] = __expf(s2);
        g_ed[i] = __expf(ALPHA * s2);
    }
}

// ---------------------------------------------------------------------------
// K2: ranks, 16 rows per block (256 blocks, ~4MB L2 traffic)
// ---------------------------------------------------------------------------
__global__ __launch_bounds__(256) void k_rank16() {
    int b = blockIdx.x;         // 256 blocks
    int tid = threadIdx.x;
    int i0 = b * 16;
    __shared__ float sv[16];
    __shared__ int scnt[16];
    if (tid < 16) { sv[tid] = g_s2[i0 + tid]; scnt[tid] = 0; }
    __syncthreads();
    int cnt[16];
    #pragma unroll
    for (int q = 0; q < 16; q++) cnt[q] = 0;
    for (int j = tid; j < KDIM; j += 256) {
        float u = g_s2[j];
        #pragma unroll
        for (int q = 0; q < 16; q++) {
            float v = sv[q];
            cnt[q] += (u < v) || (u == v && j < i0 + q);
        }
    }
    #pragma unroll
    for (int q = 0; q < 16; q++) {
        int r = cnt[q];
        #pragma unroll
        for (int o = 16; o > 0; o >>= 1) r += __shfl_down_sync(0xffffffffu, r, o);
        if ((tid & 31) == 0) atomicAdd(&scnt[q], r);
    }
    __syncthreads();
    if (tid < 16) {
        int r = scnt[tid];
        int i = i0 + tid;
        g_sorted[r] = sv[tid];
        g_sigma[r] = i;
        g_ebS[r] = g_eb[i];
        g_edS[r] = g_ed[i];
    }
}

// ---------------------------------------------------------------------------
// K3 (merged): blocks 0-255 = chunk-local vector suffix sums (scan);
// blocks 256-511 = carries computed independently from x (same accumulation
// order as the scan -> bitwise-identical totals); block 512 = scalar sscan.
// ---------------------------------------------------------------------------
__global__ __launch_bounds__(256, 2) void k_scancarry(const float* __restrict__ x) {
    int b = blockIdx.x;
    int tid = threadIdx.x;
    int lane = tid & 31, wq = tid >> 5;

    if (b < 256) {
        // ---- scan: block = chunk b ----
        int c = b;
        int col = tid * 4;
        __shared__ int ssig[CH];
        __shared__ float scb[CH], scd[CH];
        if (tid < CH) {
            int k = c * CH + tid;
            ssig[tid] = g_sigma[k];
            scb[tid] = g_ebS[k];
            scd[tid] = g_edS[k];
        }
        __syncthreads();
        float4 y[CH];
        #pragma unroll
        for (int r = 0; r < CH; r++)
            y[r] = __ldg(reinterpret_cast<const float4*>(x + (size_t)ssig[r] * NDIM + col));
        float4 aB = make_float4(0.f, 0.f, 0.f, 0.f);
        float4 aD = make_float4(0.f, 0.f, 0.f, 0.f);
        #pragma unroll
        for (int r = CH - 1; r >= 0; r--) {
            float cb = scb[r], cd = scd[r];
            aB.x = fmaf(cb, y[r].x, aB.x); aB.y = fmaf(cb, y[r].y, aB.y);
            aB.z = fmaf(cb, y[r].z, aB.z); aB.w = fmaf(cb, y[r].w, aB.w);
            aD.x = fmaf(cd, y[r].x, aD.x); aD.y = fmaf(cd, y[r].y, aD.y);
            aD.z = fmaf(cd, y[r].z, aD.z); aD.w = fmaf(cd, y[r].w, aD.w);
            size_t ro = (size_t)(c * CH + r) * NDIM + col;
            *reinterpret_cast<float4*>(g_sufB + ro) = aB;
            *reinterpret_cast<float4*>(g_sufD + ro) = aD;
        }
    } else if (b < 512) {
        // ---- carry: block = column quad; thread = chunk; totals from x ----
        int col = (b - 256) * 4;
        int c = tid;  // chunk
        __shared__ float4 wtB[8], wtD[8];

        // weights for chunk c (contiguous in sorted order)
        float4 cb4[4], cd4[4];
        int4 sg4[4];
        #pragma unroll
        for (int q = 0; q < 4; q++) {
            cb4[q] = *reinterpret_cast<const float4*>(g_ebS + c * CH + q * 4);
            cd4[q] = *reinterpret_cast<const float4*>(g_edS + c * CH + q * 4);
            sg4[q] = *reinterpret_cast<const int4*>(g_sigma + c * CH + q * 4);
        }
        int sg[16] = { sg4[0].x, sg4[0].y, sg4[0].z, sg4[0].w,
                       sg4[1].x, sg4[1].y, sg4[1].z, sg4[1].w,
                       sg4[2].x, sg4[2].y, sg4[2].z, sg4[2].w,
                       sg4[3].x, sg4[3].y, sg4[3].z, sg4[3].w };
        float cb[16] = { cb4[0].x, cb4[0].y, cb4[0].z, cb4[0].w,
                         cb4[1].x, cb4[1].y, cb4[1].z, cb4[1].w,
                         cb4[2].x, cb4[2].y, cb4[2].z, cb4[2].w,
                         cb4[3].x, cb4[3].y, cb4[3].z, cb4[3].w };
        float cd[16] = { cd4[0].x, cd4[0].y, cd4[0].z, cd4[0].w,
                         cd4[1].x, cd4[1].y, cd4[1].z, cd4[1].w,
                         cd4[2].x, cd4[2].y, cd4[2].z, cd4[2].w,
                         cd4[3].x, cd4[3].y, cd4[3].z, cd4[3].w };

        float4 y[CH];
        #pragma unroll
        for (int r = 0; r < CH; r++)
            y[r] = __ldg(reinterpret_cast<const float4*>(x + (size_t)sg[r] * NDIM + col));

        // chunk totals, SAME order as scan (r = 15 -> 0) => bitwise identical
        float4 tB = make_float4(0.f, 0.f, 0.f, 0.f);
        float4 tD = make_float4(0.f, 0.f, 0.f, 0.f);
        #pragma unroll
        for (int r = CH - 1; r >= 0; r--) {
            tB.x = fmaf(cb[r], y[r].x, tB.x); tB.y = fmaf(cb[r], y[r].y, tB.y);
            tB.z = fmaf(cb[r], y[r].z, tB.z); tB.w = fmaf(cb[r], y[r].w, tB.w);
            tD.x = fmaf(cd[r], y[r].x, tD.x); tD.y = fmaf(cd[r], y[r].y, tD.y);
            tD.z = fmaf(cd[r], y[r].z, tD.z); tD.w = fmaf(cd[r], y[r].w, tD.w);
        }

        float4 iB = suffix_shfl(tB, lane);  // inclusive suffix within warp
        float4 iD = suffix_shfl(tD, lane);
        if (lane == 0) { wtB[wq] = iB; wtD[wq] = iD; }
        __syncthreads();
        float4 gB = make_float4(0.f, 0.f, 0.f, 0.f);
        float4 gD = make_float4(0.f, 0.f, 0.f, 0.f);
        #pragma unroll
        for (int g = 0; g < 8; g++) {
            if (g > wq) {
                float4 vB = wtB[g], vD = wtD[g];
                gB.x += vB.x; gB.y += vB.y; gB.z += vB.z; gB.w += vB.w;
                gD.x += vD.x; gD.y += vD.y; gD.z += vD.z; gD.w += vD.w;
            }
        }
        float4 eB = make_float4(iB.x - tB.x + gB.x, iB.y - tB.y + gB.y,
                                iB.z - tB.z + gB.z, iB.w - tB.w + gB.w);
        float4 eD = make_float4(iD.x - tD.x + gD.x, iD.y - tD.y + gD.y,
                                iD.z - tD.z + gD.z, iD.w - tD.w + gD.w);
        *reinterpret_cast<float4*>(g_carB + (size_t)c * NDIM + col) = eB;
        *reinterpret_cast<float4*>(g_carD + (size_t)c * NDIM + col) = eD;
    } else {
        // ---- scalar suffix scans: thread t owns elems [16t, 16t+16) ----
        __shared__ float wtot[8], wsuf[8];
        #pragma unroll
        for (int pass = 0; pass < 2; pass++) {
            const float* src = pass ? g_edS : g_ebS;
            float* dst = pass ? g_sd : g_sb;
            float e[16];
            float tot = 0.f;
            #pragma unroll
            for (int q = 0; q < 16; q++) { e[q] = src[16 * tid + q]; tot += e[q]; }
            float v = tot;
            #pragma unroll
            for (int o = 1; o < 32; o <<= 1) {
                float u = __shfl_down_sync(0xffffffffu, v, o);
                if (lane + o < 32) v += u;
            }
            if (lane == 0) wtot[wq] = v;
            __syncthreads();
            if (wq == 0 && lane < 8) {
                float s = 0.f;
                #pragma unroll
                for (int q = 0; q < 8; q++) s += (q > lane) ? wtot[q] : 0.f;
                wsuf[lane] = s;
            }
            __syncthreads();
            float s = (v - tot) + wsuf[wq];
            #pragma unroll
            for (int q = 15; q >= 0; q--) {
                s += e[q];
                dst[16 * tid + q] = s;
            }
            if (tid == 0) dst[KDIM] = 0.f;
            __syncthreads();
        }
    }
}

// ---------------------------------------------------------------------------
// K4: outputs, 4 rows per block (1024 blocks -> full chip). TotD loaded once
// per block; all 4 rows' table loads issued as one batch (16 LDG in flight).
// ---------------------------------------------------------------------------
__global__ __launch_bounds__(256) void k_out(float* __restrict__ out) {
    int b = blockIdx.x;          // 1024
    int tid = threadIdx.x;
    int col = tid * 4;
    __shared__ int sT[4];
    __shared__ float sAZ[4], sCZ[4];

    float4 sD0 = *reinterpret_cast<const float4*>(g_sufD + col);
    float4 cD0 = *reinterpret_cast<const float4*>(g_carD + col);
    float4 tD = make_float4(sD0.x + cD0.x, sD0.y + cD0.y,
                            sD0.z + cD0.z, sD0.w + cD0.w);
    if (tid < 4) {
        int i = b * 4 + tid;
        float key = -g_s1[i];
        int lo = 0, hi = KDIM;
        while (lo < hi) {
            int mid = (lo + hi) >> 1;
            if (g_sorted[mid] <= key) lo = mid + 1;
            else hi = mid;
        }
        int t = lo;
        float a = g_ea[i], c = g_ec[i];
        float Z = a * g_sb[t] + c * (g_sd[0] - g_sd[t]);
        float rZ = 1.f / Z;
        sT[tid] = t;
        sAZ[tid] = a * rZ;
        sCZ[tid] = c * rZ;
    }
    __syncthreads();

    float4 sB[4], cB[4], sD[4], cD[4];
    #pragma unroll
    for (int q = 0; q < 4; q++) {
        int t = sT[q];
        int tt = (t < KDIM) ? t : 0;
        int ch = tt / CH;
        size_t ro = (size_t)tt * NDIM + col;
        size_t co = (size_t)ch * NDIM + col;
        sB[q] = *reinterpret_cast<const float4*>(g_sufB + ro);
        cB[q] = *reinterpret_cast<const float4*>(g_carB + co);
        sD[q] = *reinterpret_cast<const float4*>(g_sufD + ro);
        cD[q] = *reinterpret_cast<const float4*>(g_carD + co);
    }
    #pragma unroll
    for (int q = 0; q < 4; q++) {
        float aZ = sAZ[q], cZ = sCZ[q];
        float m = (sT[q] < KDIM) ? 1.f : 0.f;
        float4 h;
        h.x = aZ * m * (sB[q].x + cB[q].x) + cZ * (tD.x - m * (sD[q].x + cD[q].x));
        h.y = aZ * m * (sB[q].y + cB[q].y) + cZ * (tD.y - m * (sD[q].y + cD[q].y));
        h.z = aZ * m * (sB[q].z + cB[q].z) + cZ * (tD.z - m * (sD[q].z + cD[q].z));
        h.w = aZ * m * (sB[q].w + cB[q].w) + cZ * (tD.w - m * (sD[q].w + cD[q].w));
        *reinterpret_cast<float4*>(out + (size_t)(b * 4 + q) * NDIM + col) = h;
    }
}

// ---------------------------------------------------------------------------
extern "C" void kernel_launch(void* const* d_in, const int* in_sizes, int n_in,
                              void* d_out, int out_size) {
    const float* x = (const float*)d_in[0];   // (4096, 1024) fp32
    const float* w = (const float*)d_in[1];   // (2048, 1) fp32
    float* out = (float*)d_out;               // (4096, 1024) fp32

    k_scores<<<KDIM / 4, 256>>>(x, w);
    k_rank16<<<NCHUNK, 256>>>();
    k_scancarry<<<513, 256>>>(x);
    k_out<<<KDIM / 4, 256>>>(out);
}

// round 15
// speedup vs baseline: 1.0767x; 1.0430x over previous
#include <cuda_runtime.h>
#include <cuda_bf16.h>
#include <cstdint>

#define ALPHA 0.2f
#define KDIM 4096
#define NDIM 1024
#define CH 16
#define NCHUNK (KDIM / CH)   // 256

// ---------------- scratch (__device__ globals; no allocs allowed) ----------
__device__ float g_s1[KDIM], g_s2[KDIM];
__device__ float g_ea[KDIM], g_ec[KDIM];        // exp(s1), exp(0.2 s1)
__device__ float g_eb[KDIM], g_ed[KDIM];        // exp(s2), exp(0.2 s2)
__device__ float g_sorted[KDIM];                // s2 ascending
__device__ int   g_sigma[KDIM];                 // sorted rank -> original index
__device__ float g_ebS[KDIM], g_edS[KDIM];      // eb/ed in sorted order
__device__ float g_sb[KDIM + 1], g_sd[KDIM + 1];// scalar global suffix sums
__device__ float g_sufB[(size_t)KDIM * NDIM];   // chunk-local vector suffix sums
__device__ float g_sufD[(size_t)KDIM * NDIM];
__device__ float g_carB[NCHUNK * NDIM];         // exclusive chunk-suffix carries
__device__ float g_carD[NCHUNK * NDIM];
__device__ float g_totD[NDIM];                  // full TotD vector
__device__ int   g_t[KDIM];                     // per-row rank (precomputed)

__device__ __forceinline__ float4 suffix_shfl(float4 v, int lane) {
    #pragma unroll
    for (int o = 1; o < 32; o <<= 1) {
        float ux = __shfl_down_sync(0xffffffffu, v.x, o);
        float uy = __shfl_down_sync(0xffffffffu, v.y, o);
        float uz = __shfl_down_sync(0xffffffffu, v.z, o);
        float uw = __shfl_down_sync(0xffffffffu, v.w, o);
        if (lane + o < 32) { v.x += ux; v.y += uy; v.z += uz; v.w += uw; }
    }
    return v;
}

// ---------------------------------------------------------------------------
// K1: s1/s2 GEMV + exp factors. 1024 blocks x 4 rows, loads batched for MLP.
// ---------------------------------------------------------------------------
__global__ __launch_bounds__(256) void k_scores(const float* __restrict__ x,
                                                const float* __restrict__ w) {
    int b = blockIdx.x;           // 1024
    int t = threadIdx.x;          // 256 threads * float4 = 1024 cols
    int i0 = b * 4;
    const float4* w1 = reinterpret_cast<const float4*>(w);
    const float4* w2 = reinterpret_cast<const float4*>(w + NDIM);
    float4 a = __ldg(w1 + t);
    float4 bb = __ldg(w2 + t);
    float4 xv[4];
    #pragma unroll
    for (int r = 0; r < 4; r++)
        xv[r] = __ldg(reinterpret_cast<const float4*>(x + (size_t)(i0 + r) * NDIM) + t);

    __shared__ float sm1[4][8], sm2[4][8];
    #pragma unroll
    for (int r = 0; r < 4; r++) {
        float d1 = xv[r].x * a.x + xv[r].y * a.y + xv[r].z * a.z + xv[r].w * a.w;
        float d2 = xv[r].x * bb.x + xv[r].y * bb.y + xv[r].z * bb.z + xv[r].w * bb.w;
        #pragma unroll
        for (int o = 16; o > 0; o >>= 1) {
            d1 += __shfl_down_sync(0xffffffffu, d1, o);
            d2 += __shfl_down_sync(0xffffffffu, d2, o);
        }
        if ((t & 31) == 0) { sm1[r][t >> 5] = d1; sm2[r][t >> 5] = d2; }
    }
    __syncthreads();
    if (t < 4) {
        float s1 = 0.f, s2 = 0.f;
        #pragma unroll
        for (int q = 0; q < 8; q++) { s1 += sm1[t][q]; s2 += sm2[t][q]; }
        int i = i0 + t;
        g_s1[i] = s1;
        g_s2[i] = s2;
        g_ea[i] = __expf(s1);
        g_ec[i] = __expf(ALPHA * s1);
        g_eb[i] = __expf(s2);
        g_ed[i] = __expf(ALPHA * s2);
    }
}

// ---------------------------------------------------------------------------
// K2: ranks, 16 rows per block (256 blocks, ~4MB L2 traffic)
// ---------------------------------------------------------------------------
__global__ __launch_bounds__(256) void k_rank16() {
    int b = blockIdx.x;         // 256 blocks
    int tid = threadIdx.x;
    int i0 = b * 16;
    __shared__ float sv[16];
    __shared__ int scnt[16];
    if (tid < 16) { sv[tid] = g_s2[i0 + tid]; scnt[tid] = 0; }
    __syncthreads();
    int cnt[16];
    #pragma unroll
    for (int q = 0; q < 16; q++) cnt[q] = 0;
    for (int j = tid; j < KDIM; j += 256) {
        float u = g_s2[j];
        #pragma unroll
        for (int q = 0; q < 16; q++) {
            float v = sv[q];
            cnt[q] += (u < v) || (u == v && j < i0 + q);
        }
    }
    #pragma unroll
    for (int q = 0; q < 16; q++) {
        int r = cnt[q];
        #pragma unroll
        for (int o = 16; o > 0; o >>= 1) r += __shfl_down_sync(0xffffffffu, r, o);
        if ((tid & 31) == 0) atomicAdd(&scnt[q], r);
    }
    __syncthreads();
    if (tid < 16) {
        int r = scnt[tid];
        int i = i0 + tid;
        g_sorted[r] = sv[tid];
        g_sigma[r] = i;
        g_ebS[r] = g_eb[i];
        g_edS[r] = g_ed[i];
    }
}

// ---------------------------------------------------------------------------
// K3 (merged): blocks 0-255 = scan; blocks 256-511 = carries (totals from x,
// same order -> bitwise identical) + TotD; block 512 = scalar sscan;
// blocks 513-528 = per-row rank binary searches (only need g_sorted).
// ---------------------------------------------------------------------------
__global__ __launch_bounds__(256, 2) void k_scancarry(const float* __restrict__ x) {
    int b = blockIdx.x;
    int tid = threadIdx.x;
    int lane = tid & 31, wq = tid >> 5;

    if (b < 256) {
        // ---- scan: block = chunk b ----
        int c = b;
        int col = tid * 4;
        __shared__ int ssig[CH];
        __shared__ float scb[CH], scd[CH];
        if (tid < CH) {
            int k = c * CH + tid;
            ssig[tid] = g_sigma[k];
            scb[tid] = g_ebS[k];
            scd[tid] = g_edS[k];
        }
        __syncthreads();
        float4 y[CH];
        #pragma unroll
        for (int r = 0; r < CH; r++)
            y[r] = __ldg(reinterpret_cast<const float4*>(x + (size_t)ssig[r] * NDIM + col));
        float4 aB = make_float4(0.f, 0.f, 0.f, 0.f);
        float4 aD = make_float4(0.f, 0.f, 0.f, 0.f);
        #pragma unroll
        for (int r = CH - 1; r >= 0; r--) {
            float cb = scb[r], cd = scd[r];
            aB.x = fmaf(cb, y[r].x, aB.x); aB.y = fmaf(cb, y[r].y, aB.y);
            aB.z = fmaf(cb, y[r].z, aB.z); aB.w = fmaf(cb, y[r].w, aB.w);
            aD.x = fmaf(cd, y[r].x, aD.x); aD.y = fmaf(cd, y[r].y, aD.y);
            aD.z = fmaf(cd, y[r].z, aD.z); aD.w = fmaf(cd, y[r].w, aD.w);
            size_t ro = (size_t)(c * CH + r) * NDIM + col;
            *reinterpret_cast<float4*>(g_sufB + ro) = aB;
            *reinterpret_cast<float4*>(g_sufD + ro) = aD;
        }
    } else if (b < 512) {
        // ---- carry: block = column quad; thread = chunk; totals from x ----
        int col = (b - 256) * 4;
        int c = tid;  // chunk
        __shared__ float4 wtB[8], wtD[8];

        float4 cb4[4], cd4[4];
        int4 sg4[4];
        #pragma unroll
        for (int q = 0; q < 4; q++) {
            cb4[q] = *reinterpret_cast<const float4*>(g_ebS + c * CH + q * 4);
            cd4[q] = *reinterpret_cast<const float4*>(g_edS + c * CH + q * 4);
            sg4[q] = *reinterpret_cast<const int4*>(g_sigma + c * CH + q * 4);
        }
        int sg[16] = { sg4[0].x, sg4[0].y, sg4[0].z, sg4[0].w,
                       sg4[1].x, sg4[1].y, sg4[1].z, sg4[1].w,
                       sg4[2].x, sg4[2].y, sg4[2].z, sg4[2].w,
                       sg4[3].x, sg4[3].y, sg4[3].z, sg4[3].w };
        float cb[16] = { cb4[0].x, cb4[0].y, cb4[0].z, cb4[0].w,
                         cb4[1].x, cb4[1].y, cb4[1].z, cb4[1].w,
                         cb4[2].x, cb4[2].y, cb4[2].z, cb4[2].w,
                         cb4[3].x, cb4[3].y, cb4[3].z, cb4[3].w };
        float cd[16] = { cd4[0].x, cd4[0].y, cd4[0].z, cd4[0].w,
                         cd4[1].x, cd4[1].y, cd4[1].z, cd4[1].w,
                         cd4[2].x, cd4[2].y, cd4[2].z, cd4[2].w,
                         cd4[3].x, cd4[3].y, cd4[3].z, cd4[3].w };

        float4 y[CH];
        #pragma unroll
        for (int r = 0; r < CH; r++)
            y[r] = __ldg(reinterpret_cast<const float4*>(x + (size_t)sg[r] * NDIM + col));

        float4 tB = make_float4(0.f, 0.f, 0.f, 0.f);
        float4 tD = make_float4(0.f, 0.f, 0.f, 0.f);
        #pragma unroll
        for (int r = CH - 1; r >= 0; r--) {
            tB.x = fmaf(cb[r], y[r].x, tB.x); tB.y = fmaf(cb[r], y[r].y, tB.y);
            tB.z = fmaf(cb[r], y[r].z, tB.z); tB.w = fmaf(cb[r], y[r].w, tB.w);
            tD.x = fmaf(cd[r], y[r].x, tD.x); tD.y = fmaf(cd[r], y[r].y, tD.y);
            tD.z = fmaf(cd[r], y[r].z, tD.z); tD.w = fmaf(cd[r], y[r].w, tD.w);
        }

        float4 iB = suffix_shfl(tB, lane);
        float4 iD = suffix_shfl(tD, lane);
        if (lane == 0) { wtB[wq] = iB; wtD[wq] = iD; }
        __syncthreads();
        float4 gB = make_float4(0.f, 0.f, 0.f, 0.f);
        float4 gD = make_float4(0.f, 0.f, 0.f, 0.f);
        #pragma unroll
        for (int g = 0; g < 8; g++) {
            if (g > wq) {
                float4 vB = wtB[g], vD = wtD[g];
                gB.x += vB.x; gB.y += vB.y; gB.z += vB.z; gB.w += vB.w;
                gD.x += vD.x; gD.y += vD.y; gD.z += vD.z; gD.w += vD.w;
            }
        }
        float4 eB = make_float4(iB.x - tB.x + gB.x, iB.y - tB.y + gB.y,
                                iB.z - tB.z + gB.z, iB.w - tB.w + gB.w);
        float4 eD = make_float4(iD.x - tD.x + gD.x, iD.y - tD.y + gD.y,
                                iD.z - tD.z + gD.z, iD.w - tD.w + gD.w);
        *reinterpret_cast<float4*>(g_carB + (size_t)c * NDIM + col) = eB;
        *reinterpret_cast<float4*>(g_carD + (size_t)c * NDIM + col) = eD;
        if (c == 0) {
            // TotD = local chunk-0 suffix total + exclusive carry of chunk 0
            float4 tt = make_float4(tD.x + eD.x, tD.y + eD.y,
                                    tD.z + eD.z, tD.w + eD.w);
            *reinterpret_cast<float4*>(g_totD + col) = tt;
        }
    } else if (b == 512) {
        // ---- scalar suffix scans: thread t owns elems [16t, 16t+16) ----
        __shared__ float wtot[8], wsuf[8];
        #pragma unroll
        for (int pass = 0; pass < 2; pass++) {
            const float* src = pass ? g_edS : g_ebS;
            float* dst = pass ? g_sd : g_sb;
            float e[16];
            float tot = 0.f;
            #pragma unroll
            for (int q = 0; q < 16; q++) { e[q] = src[16 * tid + q]; tot += e[q]; }
            float v = tot;
            #pragma unroll
            for (int o = 1; o < 32; o <<= 1) {
                float u = __shfl_down_sync(0xffffffffu, v, o);
                if (lane + o < 32) v += u;
            }
            if (lane == 0) wtot[wq] = v;
            __syncthreads();
            if (wq == 0 && lane < 8) {
                float s = 0.f;
                #pragma unroll
                for (int q = 0; q < 8; q++) s += (q > lane) ? wtot[q] : 0.f;
                wsuf[lane] = s;
            }
            __syncthreads();
            float s = (v - tot) + wsuf[wq];
            #pragma unroll
            for (int q = 15; q >= 0; q--) {
                s += e[q];
                dst[16 * tid + q] = s;
            }
            if (tid == 0) dst[KDIM] = 0.f;
            __syncthreads();
        }
    } else {
        // ---- per-row binary searches: rows (b-513)*256 + tid ----
        int i = (b - 513) * 256 + tid;
        float key = -g_s1[i];
        int lo = 0, hi = KDIM;
        while (lo < hi) {
            int mid = (lo + hi) >> 1;
            if (g_sorted[mid] <= key) lo = mid + 1;
            else hi = mid;
        }
        g_t[i] = lo;
    }
}

// ---------------------------------------------------------------------------
// K4: outputs, 4 rows per block (1024 blocks). Rank precomputed; Z from two
// parallel loads; TotD one float4 load; table loads batched 16-deep.
// ---------------------------------------------------------------------------
__global__ __launch_bounds__(256) void k_out(float* __restrict__ out) {
    int b = blockIdx.x;          // 1024
    int tid = threadIdx.x;
    int col = tid * 4;
    __shared__ int sT[4];
    __shared__ float sAZ[4], sCZ[4];

    float4 tD = *reinterpret_cast<const float4*>(g_totD + col);
    if (tid < 4) {
        int i = b * 4 + tid;
        int t = g_t[i];
        float a = g_ea[i], c = g_ec[i];
        float Z = a * g_sb[t] + c * (g_sd[0] - g_sd[t]);
        float rZ = 1.f / Z;
        sT[tid] = t;
        sAZ[tid] = a * rZ;
        sCZ[tid] = c * rZ;
    }
    __syncthreads();

    float4 sB[4], cB[4], sD[4], cD[4];
    #pragma unroll
    for (int q = 0; q < 4; q++) {
        int t = sT[q];
        int tt = (t < KDIM) ? t : 0;
        int ch = tt / CH;
        size_t ro = (size_t)tt * NDIM + col;
        size_t co = (size_t)ch * NDIM + col;
        sB[q] = *reinterpret_cast<const float4*>(g_sufB + ro);
        cB[q] = *reinterpret_cast<const float4*>(g_carB + co);
        sD[q] = *reinterpret_cast<const float4*>(g_sufD + ro);
        cD[q] = *reinterpret_cast<const float4*>(g_carD + co);
    }
    #pragma unroll
    for (int q = 0; q < 4; q++) {
        float aZ = sAZ[q], cZ = sCZ[q];
        float m = (sT[q] < KDIM) ? 1.f : 0.f;
        float4 h;
        h.x = aZ * m * (sB[q].x + cB[q].x) + cZ * (tD.x - m * (sD[q].x + cD[q].x));
        h.y = aZ * m * (sB[q].y + cB[q].y) + cZ * (tD.y - m * (sD[q].y + cD[q].y));
        h.z = aZ * m * (sB[q].z + cB[q].z) + cZ * (tD.z - m * (sD[q].z + cD[q].z));
        h.w = aZ * m * (sB[q].w + cB[q].w) + cZ * (tD.w - m * (sD[q].w + cD[q].w));
        *reinterpret_cast<float4*>(out + (size_t)(b * 4 + q) * NDIM + col) = h;
    }
}

// ---------------------------------------------------------------------------
extern "C" void kernel_launch(void* const* d_in, const int* in_sizes, int n_in,
                              void* d_out, int out_size) {
    const float* x = (const float*)d_in[0];   // (4096, 1024) fp32
    const float* w = (const float*)d_in[1];   // (2048, 1) fp32
    float* out = (float*)d_out;               // (4096, 1024) fp32

    k_scores<<<KDIM / 4, 256>>>(x, w);
    k_rank16<<<NCHUNK, 256>>>();
    k_scancarry<<<529, 256>>>(x);
    k_out<<<KDIM / 4, 256>>>(out);
}

// round 16
// speedup vs baseline: 1.1991x; 1.1137x over previous
#include <cuda_runtime.h>
#include <cuda_bf16.h>
#include <cstdint>

#define ALPHA 0.2f
#define KDIM 4096
#define NDIM 1024
#define CH 16
#define NCHUNK (KDIM / CH)   // 256

// ---------------- scratch (__device__ globals; no allocs allowed) ----------
__device__ float g_s1[KDIM], g_s2[KDIM];
__device__ float g_ea[KDIM], g_ec[KDIM];        // exp(s1), exp(0.2 s1)
__device__ float g_eb[KDIM], g_ed[KDIM];        // exp(s2), exp(0.2 s2)
__device__ float g_sorted[KDIM];                // s2 ascending
__device__ int   g_sigma[KDIM];                 // sorted rank -> original index
__device__ float g_ebS[KDIM], g_edS[KDIM];      // eb/ed in sorted order
__device__ float g_sb[KDIM + 1], g_sd[KDIM + 1];// scalar global suffix sums
__device__ float g_sufB[(size_t)KDIM * NDIM];   // chunk-local vector suffix sums
__device__ float g_sufD[(size_t)KDIM * NDIM];
__device__ float g_carB[NCHUNK * NDIM];         // exclusive chunk-suffix carries
__device__ float g_carD[NCHUNK * NDIM];
__device__ float g_totD[NDIM];                  // full TotD vector
__device__ int   g_t[KDIM];                     // per-row rank (precomputed)

__device__ __forceinline__ float4 suffix_shfl(float4 v, int lane) {
    #pragma unroll
    for (int o = 1; o < 32; o <<= 1) {
        float ux = __shfl_down_sync(0xffffffffu, v.x, o);
        float uy = __shfl_down_sync(0xffffffffu, v.y, o);
        float uz = __shfl_down_sync(0xffffffffu, v.z, o);
        float uw = __shfl_down_sync(0xffffffffu, v.w, o);
        if (lane + o < 32) { v.x += ux; v.y += uy; v.z += uz; v.w += uw; }
    }
    return v;
}

// ---------------------------------------------------------------------------
// K1: s1/s2 GEMV + exp factors. 1024 blocks x 4 rows, loads batched for MLP.
// ---------------------------------------------------------------------------
__global__ __launch_bounds__(256) void k_scores(const float* __restrict__ x,
                                                const float* __restrict__ w) {
    int b = blockIdx.x;           // 1024
    int t = threadIdx.x;          // 256 threads * float4 = 1024 cols
    int i0 = b * 4;
    const float4* w1 = reinterpret_cast<const float4*>(w);
    const float4* w2 = reinterpret_cast<const float4*>(w + NDIM);
    float4 a = __ldg(w1 + t);
    float4 bb = __ldg(w2 + t);
    float4 xv[4];
    #pragma unroll
    for (int r = 0; r < 4; r++)
        xv[r] = __ldg(reinterpret_cast<const float4*>(x + (size_t)(i0 + r) * NDIM) + t);

    __shared__ float sm1[4][8], sm2[4][8];
    #pragma unroll
    for (int r = 0; r < 4; r++) {
        float d1 = xv[r].x * a.x + xv[r].y * a.y + xv[r].z * a.z + xv[r].w * a.w;
        float d2 = xv[r].x * bb.x + xv[r].y * bb.y + xv[r].z * bb.z + xv[r].w * bb.w;
        #pragma unroll
        for (int o = 16; o > 0; o >>= 1) {
            d1 += __shfl_down_sync(0xffffffffu, d1, o);
            d2 += __shfl_down_sync(0xffffffffu, d2, o);
        }
        if ((t & 31) == 0) { sm1[r][t >> 5] = d1; sm2[r][t >> 5] = d2; }
    }
    __syncthreads();
    if (t < 4) {
        float s1 = 0.f, s2 = 0.f;
        #pragma unroll
        for (int q = 0; q < 8; q++) { s1 += sm1[t][q]; s2 += sm2[t][q]; }
        int i = i0 + t;
        g_s1[i] = s1;
        g_s2[i] = s2;
        g_ea[i] = __expf(s1);
        g_ec[i] = __expf(ALPHA * s1);
        g_eb[i] = __expf(s2);
        g_ed[i] = __expf(ALPHA * s2);
    }
}

// ---------------------------------------------------------------------------
// K2: ranks, 16 rows per block (256 blocks, ~4MB L2 traffic)
// ---------------------------------------------------------------------------
__global__ __launch_bounds__(256) void k_rank16() {
    int b = blockIdx.x;         // 256 blocks
    int tid = threadIdx.x;
    int i0 = b * 16;
    __shared__ float sv[16];
    __shared__ int scnt[16];
    if (tid < 16) { sv[tid] = g_s2[i0 + tid]; scnt[tid] = 0; }
    __syncthreads();
    int cnt[16];
    #pragma unroll
    for (int q = 0; q < 16; q++) cnt[q] = 0;
    for (int j = tid; j < KDIM; j += 256) {
        float u = g_s2[j];
        #pragma unroll
        for (int q = 0; q < 16; q++) {
            float v = sv[q];
            cnt[q] += (u < v) || (u == v && j < i0 + q);
        }
    }
    #pragma unroll
    for (int q = 0; q < 16; q++) {
        int r = cnt[q];
        #pragma unroll
        for (int o = 16; o > 0; o >>= 1) r += __shfl_down_sync(0xffffffffu, r, o);
        if ((tid & 31) == 0) atomicAdd(&scnt[q], r);
    }
    __syncthreads();
    if (tid < 16) {
        int r = scnt[tid];
        int i = i0 + tid;
        g_sorted[r] = sv[tid];
        g_sigma[r] = i;
        g_ebS[r] = g_eb[i];
        g_edS[r] = g_ed[i];
    }
}

// ---------------------------------------------------------------------------
// K3 (merged): blocks 0-255 = scan (two 8-row batches -> ~64 regs, occ 4);
// blocks 256-511 = carries (totals from x, same order -> bitwise identical)
// + TotD; block 512 = scalar sscan; blocks 513-528 = per-row rank searches.
// ---------------------------------------------------------------------------
__global__ __launch_bounds__(256, 4) void k_scancarry(const float* __restrict__ x) {
    int b = blockIdx.x;
    int tid = threadIdx.x;
    int lane = tid & 31, wq = tid >> 5;

    if (b < 256) {
        // ---- scan: block = chunk b, ranks processed 15..0 in 2 batches ----
        int c = b;
        int col = tid * 4;
        __shared__ int ssig[CH];
        __shared__ float scb[CH], scd[CH];
        if (tid < CH) {
            int k = c * CH + tid;
            ssig[tid] = g_sigma[k];
            scb[tid] = g_ebS[k];
            scd[tid] = g_edS[k];
        }
        __syncthreads();
        float4 aB = make_float4(0.f, 0.f, 0.f, 0.f);
        float4 aD = make_float4(0.f, 0.f, 0.f, 0.f);
        #pragma unroll
        for (int half = 1; half >= 0; half--) {
            float4 y[8];
            #pragma unroll
            for (int q = 0; q < 8; q++)
                y[q] = __ldg(reinterpret_cast<const float4*>(
                    x + (size_t)ssig[half * 8 + q] * NDIM + col));
            #pragma unroll
            for (int q = 7; q >= 0; q--) {
                int r = half * 8 + q;
                float cb = scb[r], cd = scd[r];
                aB.x = fmaf(cb, y[q].x, aB.x); aB.y = fmaf(cb, y[q].y, aB.y);
                aB.z = fmaf(cb, y[q].z, aB.z); aB.w = fmaf(cb, y[q].w, aB.w);
                aD.x = fmaf(cd, y[q].x, aD.x); aD.y = fmaf(cd, y[q].y, aD.y);
                aD.z = fmaf(cd, y[q].z, aD.z); aD.w = fmaf(cd, y[q].w, aD.w);
                size_t ro = (size_t)(c * CH + r) * NDIM + col;
                *reinterpret_cast<float4*>(g_sufB + ro) = aB;
                *reinterpret_cast<float4*>(g_sufD + ro) = aD;
            }
        }
    } else if (b < 512) {
        // ---- carry: block = column quad; thread = chunk; totals from x ----
        int col = (b - 256) * 4;
        int c = tid;  // chunk
        __shared__ float4 wtB[8], wtD[8];

        float4 tB = make_float4(0.f, 0.f, 0.f, 0.f);
        float4 tD = make_float4(0.f, 0.f, 0.f, 0.f);
        #pragma unroll
        for (int half = 1; half >= 0; half--) {
            float cb[8], cd[8];
            int sg[8];
            #pragma unroll
            for (int q = 0; q < 8; q += 4) {
                float4 cbv = *reinterpret_cast<const float4*>(g_ebS + c * CH + half * 8 + q);
                float4 cdv = *reinterpret_cast<const float4*>(g_edS + c * CH + half * 8 + q);
                int4 sgv = *reinterpret_cast<const int4*>(g_sigma + c * CH + half * 8 + q);
                cb[q] = cbv.x; cb[q + 1] = cbv.y; cb[q + 2] = cbv.z; cb[q + 3] = cbv.w;
                cd[q] = cdv.x; cd[q + 1] = cdv.y; cd[q + 2] = cdv.z; cd[q + 3] = cdv.w;
                sg[q] = sgv.x; sg[q + 1] = sgv.y; sg[q + 2] = sgv.z; sg[q + 3] = sgv.w;
            }
            float4 y[8];
            #pragma unroll
            for (int q = 0; q < 8; q++)
                y[q] = __ldg(reinterpret_cast<const float4*>(
                    x + (size_t)sg[q] * NDIM + col));
            #pragma unroll
            for (int q = 7; q >= 0; q--) {
                tB.x = fmaf(cb[q], y[q].x, tB.x); tB.y = fmaf(cb[q], y[q].y, tB.y);
                tB.z = fmaf(cb[q], y[q].z, tB.z); tB.w = fmaf(cb[q], y[q].w, tB.w);
                tD.x = fmaf(cd[q], y[q].x, tD.x); tD.y = fmaf(cd[q], y[q].y, tD.y);
                tD.z = fmaf(cd[q], y[q].z, tD.z); tD.w = fmaf(cd[q], y[q].w, tD.w);
            }
        }

        float4 iB = suffix_shfl(tB, lane);
        float4 iD = suffix_shfl(tD, lane);
        if (lane == 0) { wtB[wq] = iB; wtD[wq] = iD; }
        __syncthreads();
        float4 gB = make_float4(0.f, 0.f, 0.f, 0.f);
        float4 gD = make_float4(0.f, 0.f, 0.f, 0.f);
        #pragma unroll
        for (int g = 0; g < 8; g++) {
            if (g > wq) {
                float4 vB = wtB[g], vD = wtD[g];
                gB.x += vB.x; gB.y += vB.y; gB.z += vB.z; gB.w += vB.w;
                gD.x += vD.x; gD.y += vD.y; gD.z += vD.z; gD.w += vD.w;
            }
        }
        float4 eB = make_float4(iB.x - tB.x + gB.x, iB.y - tB.y + gB.y,
                                iB.z - tB.z + gB.z, iB.w - tB.w + gB.w);
        float4 eD = make_float4(iD.x - tD.x + gD.x, iD.y - tD.y + gD.y,
                                iD.z - tD.z + gD.z, iD.w - tD.w + gD.w);
        *reinterpret_cast<float4*>(g_carB + (size_t)c * NDIM + col) = eB;
        *reinterpret_cast<float4*>(g_carD + (size_t)c * NDIM + col) = eD;
        if (c == 0) {
            float4 tt = make_float4(tD.x + eD.x, tD.y + eD.y,
                                    tD.z + eD.z, tD.w + eD.w);
            *reinterpret_cast<float4*>(g_totD + col) = tt;
        }
    } else if (b == 512) {
        // ---- scalar suffix scans: thread t owns elems [16t, 16t+16) ----
        __shared__ float wtot[8], wsuf[8];
        #pragma unroll
        for (int pass = 0; pass < 2; pass++) {
            const float* src = pass ? g_edS : g_ebS;
            float* dst = pass ? g_sd : g_sb;
            float e[16];
            float tot = 0.f;
            #pragma unroll
            for (int q = 0; q < 16; q++) { e[q] = src[16 * tid + q]; tot += e[q]; }
            float v = tot;
            #pragma unroll
            for (int o = 1; o < 32; o <<= 1) {
                float u = __shfl_down_sync(0xffffffffu, v, o);
                if (lane + o < 32) v += u;
            }
            if (lane == 0) wtot[wq] = v;
            __syncthreads();
            if (wq == 0 && lane < 8) {
                float s = 0.f;
                #pragma unroll
                for (int q = 0; q < 8; q++) s += (q > lane) ? wtot[q] : 0.f;
                wsuf[lane] = s;
            }
            __syncthreads();
            float s = (v - tot) + wsuf[wq];
            #pragma unroll
            for (int q = 15; q >= 0; q--) {
                s += e[q];
                dst[16 * tid + q] = s;
            }
            if (tid == 0) dst[KDIM] = 0.f;
            __syncthreads();
        }
    } else {
        // ---- per-row binary searches: rows (b-513)*256 + tid ----
        int i = (b - 513) * 256 + tid;
        float key = -g_s1[i];
        int lo = 0, hi = KDIM;
        while (lo < hi) {
            int mid = (lo + hi) >> 1;
            if (g_sorted[mid] <= key) lo = mid + 1;
            else hi = mid;
        }
        g_t[i] = lo;
    }
}

// ---------------------------------------------------------------------------
// K4: outputs, 2 rows per block (2048 blocks). Rank precomputed; table loads
// batched 8-deep per thread.
// ---------------------------------------------------------------------------
__global__ __launch_bounds__(256) void k_out(float* __restrict__ out) {
    int b = blockIdx.x;          // 2048
    int tid = threadIdx.x;
    int col = tid * 4;
    __shared__ int sT[2];
    __shared__ float sAZ[2], sCZ[2];

    float4 tD = *reinterpret_cast<const float4*>(g_totD + col);
    if (tid < 2) {
        int i = b * 2 + tid;
        int t = g_t[i];
        float a = g_ea[i], c = g_ec[i];
        float Z = a * g_sb[t] + c * (g_sd[0] - g_sd[t]);
        float rZ = 1.f / Z;
        sT[tid] = t;
        sAZ[tid] = a * rZ;
        sCZ[tid] = c * rZ;
    }
    __syncthreads();

    float4 sB[2], cB[2], sD[2], cD[2];
    #pragma unroll
    for (int q = 0; q < 2; q++) {
        int t = sT[q];
        int tt = (t < KDIM) ? t : 0;
        int ch = tt / CH;
        size_t ro = (size_t)tt * NDIM + col;
        size_t co = (size_t)ch * NDIM + col;
        sB[q] = *reinterpret_cast<const float4*>(g_sufB + ro);
        cB[q] = *reinterpret_cast<const float4*>(g_carB + co);
        sD[q] = *reinterpret_cast<const float4*>(g_sufD + ro);
        cD[q] = *reinterpret_cast<const float4*>(g_carD + co);
    }
    #pragma unroll
    for (int q = 0; q < 2; q++) {
        float aZ = sAZ[q], cZ = sCZ[q];
        float m = (sT[q] < KDIM) ? 1.f : 0.f;
        float4 h;
        h.x = aZ * m * (sB[q].x + cB[q].x) + cZ * (tD.x - m * (sD[q].x + cD[q].x));
        h.y = aZ * m * (sB[q].y + cB[q].y) + cZ * (tD.y - m * (sD[q].y + cD[q].y));
        h.z = aZ * m * (sB[q].z + cB[q].z) + cZ * (tD.z - m * (sD[q].z + cD[q].z));
        h.w = aZ * m * (sB[q].w + cB[q].w) + cZ * (tD.w - m * (sD[q].w + cD[q].w));
        *reinterpret_cast<float4*>(out + (size_t)(b * 2 + q) * NDIM + col) = h;
    }
}

// ---------------------------------------------------------------------------
extern "C" void kernel_launch(void* const* d_in, const int* in_sizes, int n_in,
                              void* d_out, int out_size) {
    const float* x = (const float*)d_in[0];   // (4096, 1024) fp32
    const float* w = (const float*)d_in[1];   // (2048, 1) fp32
    float* out = (float*)d_out;               // (4096, 1024) fp32

    k_scores<<<KDIM / 4, 256>>>(x, w);
    k_rank16<<<NCHUNK, 256>>>();
    k_scancarry<<<529, 256>>>(x);
    k_out<<<KDIM / 2, 256>>>(out);
}